// round 17
// baseline (speedup 1.0000x reference)
#include <cuda_runtime.h>
#include <math.h>

#define NUM_FIELDS 10
#define VOCAB      100000
#define EMBED      8
#define BATCH      16384

#define TPR            16                // threads cooperating on one row
#define ROWS_PER_BLOCK 8
#define THREADS        (TPR * ROWS_PER_BLOCK)   // 128
#define NPAIRS         45
#define PAIRS_PER_T    3                 // ceil(45/16)

// Two-tier L2 policy (measured optimum): slices with offset < CACHE_CUT_OFF
// pinned via L2::evict_last 256-bit loads; the rest stream evict-first.
#define CACHE_CUT_OFF  (48 * VOCAB)

struct V8 { float f[8]; };

// L2-pinned 32-byte load: one 256-bit ld with lowest L2 eviction priority.
__device__ __forceinline__ V8 ldg_pin32(const float* p) {
    unsigned long long a, b, c, d;
    asm("ld.global.nc.L2::evict_last.v4.b64 {%0,%1,%2,%3}, [%4];"
        : "=l"(a), "=l"(b), "=l"(c), "=l"(d)
        : "l"(p));
    V8 v;
    v.f[0] = __uint_as_float((unsigned)(a));
    v.f[1] = __uint_as_float((unsigned)(a >> 32));
    v.f[2] = __uint_as_float((unsigned)(b));
    v.f[3] = __uint_as_float((unsigned)(b >> 32));
    v.f[4] = __uint_as_float((unsigned)(c));
    v.f[5] = __uint_as_float((unsigned)(c >> 32));
    v.f[6] = __uint_as_float((unsigned)(d));
    v.f[7] = __uint_as_float((unsigned)(d >> 32));
    return v;
}

// Streaming 32-byte load (evict-first) via two 128-bit loads.
__device__ __forceinline__ V8 ldg_stream32(const float* p) {
    const float4 lo = __ldcs(reinterpret_cast<const float4*>(p));
    const float4 hi = __ldcs(reinterpret_cast<const float4*>(p) + 1);
    V8 v;
    v.f[0] = lo.x; v.f[1] = lo.y; v.f[2] = lo.z; v.f[3] = lo.w;
    v.f[4] = hi.x; v.f[5] = hi.y; v.f[6] = hi.z; v.f[7] = hi.w;
    return v;
}

__device__ __forceinline__ V8 ld_tiered(const float* p, int offset) {
    return (offset < CACHE_CUT_OFF) ? ldg_pin32(p) : ldg_stream32(p);
}

// Allow 64 regs/thread so ~6 V8 loads can be in flight per thread (MLP),
// instead of the 2-3 permitted by the previous 32-reg cap.
__global__ __launch_bounds__(THREADS, 8)
void ffm_kernel(const int*   __restrict__ x,
                const float* __restrict__ bias,
                const float* __restrict__ L,
                const float* __restrict__ V,
                float*       __restrict__ out)
{
    __shared__ int sx[ROWS_PER_BLOCK][NUM_FIELDS];
    __shared__ int sI[NPAIRS], sJ[NPAIRS];
    __shared__ int sOij[NPAIRS], sOji[NPAIRS];

    const int tid = threadIdx.x;

    // ---- build pair table (once per block) ----
    if (tid < NPAIRS) {
        int p = tid;
        int i = 0, rem = p;
        while (rem >= (NUM_FIELDS - 1 - i)) { rem -= (NUM_FIELDS - 1 - i); ++i; }
        int j = i + 1 + rem;
        sI[p] = i;
        sJ[p] = j;
        sOij[p] = (i * NUM_FIELDS + j) * VOCAB;
        sOji[p] = (j * NUM_FIELDS + i) * VOCAB;
    }

    // ---- stage x tile for this block's rows ----
    const int row0 = blockIdx.x * ROWS_PER_BLOCK;
    for (int k = tid; k < ROWS_PER_BLOCK * NUM_FIELDS; k += THREADS) {
        ((int*)sx)[k] = x[row0 * NUM_FIELDS + k];
    }
    __syncthreads();

    const int r = tid / TPR;   // local row
    const int t = tid % TPR;   // slot within row group
    const int b = row0 + r;
    const int* xs = sx[r];

    // ---- second order: compute all 6 addresses, then issue ALL 6 loads,
    //      then do the math. Maximizes outstanding loads per thread. ----
    const int p0 = t;
    const int p1 = t + TPR;
    const int p2 = (t + 2 * TPR < NPAIRS) ? (t + 2 * TPR) : p0;  // lanes 13-15 redo p0
    const bool has2 = (t + 2 * TPR < NPAIRS);

    const int oA0 = sOij[p0], oB0 = sOji[p0];
    const int oA1 = sOij[p1], oB1 = sOji[p1];
    const int oA2 = sOij[p2], oB2 = sOji[p2];

    const float* A0 = V + (size_t)(oA0 + xs[sI[p0]]) * EMBED;
    const float* B0 = V + (size_t)(oB0 + xs[sJ[p0]]) * EMBED;
    const float* A1 = V + (size_t)(oA1 + xs[sI[p1]]) * EMBED;
    const float* B1 = V + (size_t)(oB1 + xs[sJ[p1]]) * EMBED;
    const float* A2 = V + (size_t)(oA2 + xs[sI[p2]]) * EMBED;
    const float* B2 = V + (size_t)(oB2 + xs[sJ[p2]]) * EMBED;

    const V8 a0 = ld_tiered(A0, oA0);
    const V8 b0 = ld_tiered(B0, oB0);
    const V8 a1 = ld_tiered(A1, oA1);
    const V8 b1 = ld_tiered(B1, oB1);
    const V8 a2 = ld_tiered(A2, oA2);
    const V8 b2 = ld_tiered(B2, oB2);

    float acc = 0.0f;
    #pragma unroll
    for (int e = 0; e < 8; ++e) acc += a0.f[e] * b0.f[e];
    #pragma unroll
    for (int e = 0; e < 8; ++e) acc += a1.f[e] * b1.f[e];
    if (has2) {
        float acc2 = 0.0f;
        #pragma unroll
        for (int e = 0; e < 8; ++e) acc2 += a2.f[e] * b2.f[e];
        acc += acc2;
    }

    // ---- first order: field t (only t < 10 participates) ----
    if (t < NUM_FIELDS) {
        acc += __ldg(&L[t * VOCAB + xs[t]]);
    }

    // ---- reduce across the 16-lane row group ----
    acc += __shfl_down_sync(0xffffffffu, acc, 8, 16);
    acc += __shfl_down_sync(0xffffffffu, acc, 4, 16);
    acc += __shfl_down_sync(0xffffffffu, acc, 2, 16);
    acc += __shfl_down_sync(0xffffffffu, acc, 1, 16);

    if (t == 0 && b < BATCH) {
        const float z = acc + __ldg(bias);
        out[b] = 1.0f / (1.0f + expf(-z));
    }
}

extern "C" void kernel_launch(void* const* d_in, const int* in_sizes, int n_in,
                              void* d_out, int out_size)
{
    // Bind inputs by element count (robust to metadata ordering):
    //   x: 16384*10 = 163840 int32
    //   bias: 1 float32
    //   L: 10*100000 = 1,000,000 float32
    //   V: 10*10*100000*8 = 80,000,000 float32
    const int*   x    = nullptr;
    const float* bias = nullptr;
    const float* L    = nullptr;
    const float* V    = nullptr;
    for (int i = 0; i < n_in; ++i) {
        switch (in_sizes[i]) {
            case 163840:   x    = (const int*)  d_in[i]; break;
            case 1:        bias = (const float*)d_in[i]; break;
            case 1000000:  L    = (const float*)d_in[i]; break;
            case 80000000: V    = (const float*)d_in[i]; break;
            default: break;
        }
    }
    float* out = (float*)d_out;

    const int grid = BATCH / ROWS_PER_BLOCK;   // 2048
    ffm_kernel<<<grid, THREADS>>>(x, bias, L, V, out);
}